// round 12
// baseline (speedup 1.0000x reference)
#include <cuda_runtime.h>
#include <cuda_fp16.h>
#include <cstdint>

// Problem dims
#define S_DIM   32
#define B_DIM   256
#define IN_DIM  1024
#define OUT_DIM 1024

// ---------------------------------------------------------------------------
// Scratch (device globals)
// ---------------------------------------------------------------------------
__device__ __align__(128) __half g_xf16[(size_t)S_DIM * B_DIM * IN_DIM];   // 17 MB
// Packed (mu01,sg01,mu23,sg23) half2 quads, one uint4 per 4 weights: 4 MB.
__device__ __align__(128) uint4  g_msp[(size_t)OUT_DIM * IN_DIM / 4];

__device__ __forceinline__ float softplusf(float x) {
    return (x > 15.0f) ? x : log1pf(expf(x));
}

__device__ __forceinline__ uint32_t smem_to_u32(const void* smem_ptr) {
    uint32_t addr;
    asm("{ .reg .u64 tmp; cvta.to.shared.u64 tmp, %1; cvt.u32.u64 %0, tmp; }"
        : "=r"(addr) : "l"(smem_ptr));
    return addr;
}

__device__ __forceinline__ void cp_async16(uint32_t smem_dst, const void* gptr) {
    asm volatile("cp.async.cg.shared.global [%0], [%1], 16;"
                 :: "r"(smem_dst), "l"(gptr) : "memory");
}

__device__ __forceinline__ void ldmatrix_x4(uint32_t r[4], uint32_t addr) {
    asm volatile("ldmatrix.sync.aligned.m8n8.x4.shared.b16 {%0,%1,%2,%3}, [%4];"
                 : "=r"(r[0]), "=r"(r[1]), "=r"(r[2]), "=r"(r[3]) : "r"(addr));
}

__device__ __forceinline__ void mma16816(float c[4],
                                         const uint32_t a[4],
                                         uint32_t b0, uint32_t b1) {
    asm volatile(
        "mma.sync.aligned.m16n8k16.row.col.f32.f16.f16.f32 "
        "{%0,%1,%2,%3}, {%4,%5,%6,%7}, {%8,%9}, {%0,%1,%2,%3};"
        : "+f"(c[0]), "+f"(c[1]), "+f"(c[2]), "+f"(c[3])
        : "r"(a[0]), "r"(a[1]), "r"(a[2]), "r"(a[3]), "r"(b0), "r"(b1));
}

// SW128 swizzle: byte address of 16B-quad (row, colq) in a 128-row x 128B tile.
__device__ __forceinline__ uint32_t sw128(int row, int colq) {
    return ((uint32_t)row << 7) + ((uint32_t)((colq ^ (row & 7)) & 7) << 4);
}

__device__ __forceinline__ uint32_t h2u(__half2 h) {
    return *reinterpret_cast<uint32_t*>(&h);
}
__device__ __forceinline__ __half2 u2h(uint32_t u) {
    return *reinterpret_cast<__half2*>(&u);
}

// ---------------------------------------------------------------------------
// Kernel 1 (prep): blocks [0,8192): x fp32->fp16.
//                  blocks [8192,9216): g_msp packed mu/sigma half2 quads.
// ---------------------------------------------------------------------------
__global__ __launch_bounds__(256)
void prep_kernel(const float* __restrict__ input,
                 const float* __restrict__ wmu,
                 const float* __restrict__ wrho)
{
    if (blockIdx.x < 8192) {
        const int e4 = blockIdx.x * 256 + threadIdx.x;
        const float4 x = *reinterpret_cast<const float4*>(input + (size_t)e4 * 4);
        __half2 h0 = __floats2half2_rn(x.x, x.y);
        __half2 h1 = __floats2half2_rn(x.z, x.w);
        uint2 o;
        o.x = h2u(h0);
        o.y = h2u(h1);
        reinterpret_cast<uint2*>(g_xf16)[e4] = o;
    } else {
        const int q = (blockIdx.x - 8192) * 256 + threadIdx.x;  // 0..262143
        const float4 m = *reinterpret_cast<const float4*>(wmu + (size_t)q * 4);
        const float4 r = *reinterpret_cast<const float4*>(wrho + (size_t)q * 4);
        uint4 o;
        o.x = h2u(__floats2half2_rn(m.x, m.y));
        o.y = h2u(__floats2half2_rn(softplusf(r.x), softplusf(r.y)));
        o.z = h2u(__floats2half2_rn(m.z, m.w));
        o.w = h2u(__floats2half2_rn(softplusf(r.z), softplusf(r.w)));
        g_msp[q] = o;
    }
}

// ---------------------------------------------------------------------------
// Kernel 2: FUSED variational GEMM (R9 mainloop + in-loop B generation).
// A tile: cp.async from g_xf16, 3-stage ring. B tile: generated per chunk:
//   w_h2 = hfma2(sigma_h2, eps_h2, mu_h2), eps LDG.cg one chunk ahead,
//   mu/sigma from packed g_msp (L2-resident), double-buffered B (2 x 16KB).
// CTA 128x128, KC=64, 16 chunks, 8 warps (2x4), 2 CTAs/SM.
// Grid: (ntile=8, mtile=2, s=32) = 512 CTAs.
// ---------------------------------------------------------------------------
#define KC 64
#define NCHUNK (IN_DIM / KC)          // 16
#define TILE_BYTES (128 * 128)        // 16 KB
#define B_OFF (3 * TILE_BYTES)        // B stages after 3 A stages
#define GEMM_DYN_SMEM (1024 + 3 * TILE_BYTES + 2 * TILE_BYTES)   // ~81 KB

__global__ __launch_bounds__(256, 2)
void gemm_fused_kernel(const float* __restrict__ epsw,
                       const float* __restrict__ bias_mu,
                       const float* __restrict__ bias_rho,
                       const float* __restrict__ eps_b,
                       float* __restrict__ out)
{
    extern __shared__ char dynsmem[];
    __shared__ float s_bias[128];

    const int tid = threadIdx.x;
    const int wid = tid >> 5;
    const int lid = tid & 31;
    const int ntile = blockIdx.x;   // 0..7
    const int mtile = blockIdx.y;   // 0..1
    const int s     = blockIdx.z;   // 0..31

    uint32_t base = smem_to_u32(dynsmem);
    base = (base + 1023u) & ~1023u;
    const uint32_t smA0 = base;                 // A stage st: +st*16KB
    const uint32_t smB0 = base + B_OFF;         // B stage b: +b*16KB

    if (tid < 128) {
        const int o = ntile * 128 + tid;
        s_bias[tid] = fmaf(softplusf(bias_rho[o]), eps_b[s * OUT_DIM + o], bias_mu[o]);
    }

    const __half* Ag = g_xf16 + (size_t)(s * B_DIM + mtile * 128) * IN_DIM;

    // ---- A copy mapping: j=0..3, row = (tid>>3) + 32j, kq = tid&7 ----
    const int a_r0 = tid >> 3;
    const int a_kq = tid & 7;
    const uint32_t a_dst0 = sw128(a_r0, a_kq);               // + j*4096
    const __half* a_src0 = Ag + (size_t)a_r0 * IN_DIM + a_kq * 8;  // + j*32768 + c*KC

    // ---- Convert mapping: j=0..7, row = (tid>>4) + 16j, qc = tid&15 ----
    // Thread owns 4 weights (k = qc*4..qc*4+3) in each of 8 rows.
    const int cv_r0 = tid >> 4;          // 0..15
    const int cv_qc = tid & 15;          // 0..15
    const int cv_orow0 = ntile * 128 + cv_r0;
    const float* epsC = epsw + ((size_t)s * OUT_DIM + cv_orow0) * IN_DIM + cv_qc * 4;
    // eps addr per j: epsC + j*16*IN_DIM + c*KC
    const uint4* mspC = g_msp + (size_t)cv_orow0 * 256 + cv_qc;
    // msp addr per j: mspC + j*16*256 + c*16
    const uint32_t cv_sts0 = sw128(cv_r0, cv_qc >> 1) + (uint32_t)(cv_qc & 1) * 8;
    // STS addr per j: + j*2048   (row+16 keeps row&7, +16 rows * 128B)

    // ---- MMA fragment addressing (R9) ----
    const int wm_idx = wid >> 2;
    const int wn_idx = wid & 3;
    uint32_t a_base[4];
    #pragma unroll
    for (int mi = 0; mi < 4; ++mi) {
        const int row = wm_idx * 64 + mi * 16 + (lid & 15);
        a_base[mi] = sw128(row, lid >> 4);
    }
    uint32_t b_base[2];
    #pragma unroll
    for (int g = 0; g < 2; ++g) {
        const int row = wn_idx * 32 + g * 16 + ((lid >> 4) << 3) + (lid & 7);
        b_base[g] = sw128(row, (lid >> 3) & 1);
    }

    float acc[4][4][4];
    #pragma unroll
    for (int mi = 0; mi < 4; ++mi)
        #pragma unroll
        for (int ni = 0; ni < 4; ++ni)
            #pragma unroll
            for (int k = 0; k < 4; ++k)
                acc[mi][ni][k] = 0.0f;

    auto issue_A = [&](int c, int st) {
        const uint32_t sa = smA0 + (uint32_t)st * TILE_BYTES;
        #pragma unroll
        for (int j = 0; j < 4; ++j)
            cp_async16(sa + a_dst0 + j * 4096, a_src0 + (size_t)j * 32768 + c * KC);
        asm volatile("cp.async.commit_group;" ::: "memory");
    };

    // eps held as fp16: eh[j] = {e01, e23} half2 pair for row j, chunk c+1.
    uint2 eh[8];
    auto load_eps = [&](int c) {
        #pragma unroll
        for (int j = 0; j < 8; ++j) {
            const float4 e = __ldcg(reinterpret_cast<const float4*>(
                                 epsC + (size_t)j * 16 * IN_DIM + c * KC));
            eh[j].x = h2u(__floats2half2_rn(e.x, e.y));
            eh[j].y = h2u(__floats2half2_rn(e.z, e.w));
        }
    };

    // ms half-load: msv[0..3] = packed quads for rows j = 4h..4h+3 of chunk c.
    uint4 msv[4];
    auto load_ms = [&](int h, int c) {
        #pragma unroll
        for (int j = 0; j < 4; ++j)
            msv[j] = __ldcg(mspC + (size_t)(4 * h + j) * 16 * 256 + c * 16);
    };

    // Convert 4 rows (j = 4h..4h+3) into B stage bsel using held eh + msv.
    auto convert_half = [&](int h, int bsel) {
        const uint32_t sb = smB0 + (uint32_t)bsel * TILE_BYTES;
        #pragma unroll
        for (int j = 0; j < 4; ++j) {
            const int jj = 4 * h + j;
            const uint4 ms = msv[j];
            const __half2 w01 = __hfma2(u2h(ms.y), u2h(eh[jj].x), u2h(ms.x));
            const __half2 w23 = __hfma2(u2h(ms.w), u2h(eh[jj].y), u2h(ms.z));
            asm volatile("st.shared.v2.b32 [%0], {%1, %2};"
                         :: "r"(sb + cv_sts0 + (uint32_t)jj * 2048),
                            "r"(h2u(w01)), "r"(h2u(w23))
                         : "memory");
        }
    };

    // ---- Prologue ----
    issue_A(0, 0);
    issue_A(1, 1);
    // B(0) -> stage 0 (direct: load eps(0), ms(0), convert)
    load_eps(0);
    load_ms(0, 0);
    convert_half(0, 0);
    load_ms(1, 0);
    convert_half(1, 0);
    // eps for chunk 1 (consumed during chunk 0)
    load_eps(1);
    __syncthreads();   // B(0) visible to all warps

    int st = 0;                       // A stage of chunk c (c % 3)
    for (int c = 0; c < NCHUNK; ++c) {
        if (c == NCHUNK - 1) {
            asm volatile("cp.async.wait_group 0;" ::: "memory");
        } else {
            asm volatile("cp.async.wait_group 1;" ::: "memory");
        }
        __syncthreads();   // A(c) visible; B(c) visible; B stage (c+1)&1 free

        if (c + 2 < NCHUNK) {
            int st2 = st + 2; if (st2 >= 3) st2 -= 3;
            issue_A(c + 2, st2);
        }
        if (c + 1 < NCHUNK) load_ms(0, c + 1);

        const uint32_t sa = smA0 + (uint32_t)st * TILE_BYTES;
        const uint32_t sb = smB0 + (uint32_t)(c & 1) * TILE_BYTES;
        const int bnext = (c + 1) & 1;

        #pragma unroll
        for (int ks = 0; ks < 4; ++ks) {
            const uint32_t kx = (uint32_t)(ks << 5);
            uint32_t ar[4][4];
            uint32_t br[2][4];
            #pragma unroll
            for (int mi = 0; mi < 4; ++mi)
                ldmatrix_x4(ar[mi], sa + (a_base[mi] ^ kx));
            #pragma unroll
            for (int g = 0; g < 2; ++g)
                ldmatrix_x4(br[g], sb + (b_base[g] ^ kx));

            #pragma unroll
            for (int mi = 0; mi < 4; ++mi) {
                #pragma unroll
                for (int ni = 0; ni < 4; ++ni) {
                    const int g = ni >> 1;
                    const int h = (ni & 1) << 1;
                    mma16816(acc[mi][ni], ar[mi], br[g][h + 0], br[g][h + 1]);
                }
            }

            // Interleaved B-production / eps prefetch between MMA bundles.
            if (ks == 0 && c + 1 < NCHUNK) {
                convert_half(0, bnext);   // rows 0..63 of B(c+1)
                load_ms(1, c + 1);
            } else if (ks == 1 && c + 1 < NCHUNK) {
                convert_half(1, bnext);   // rows 64..127 of B(c+1)
            } else if (ks == 2 && c + 2 < NCHUNK) {
                load_eps(c + 2);          // eps for B(c+2), used next chunk
            }
        }

        if (++st >= 3) st -= 3;
    }

    // Epilogue: add bias, store fp32 (R9).
    const int row_in = (lid >> 2);
    const int col_in = (lid & 3) * 2;
    #pragma unroll
    for (int mi = 0; mi < 4; ++mi) {
        const int m0 = mtile * 128 + wm_idx * 64 + mi * 16 + row_in;
        float* orow0 = out + ((size_t)(s * B_DIM + m0)     * OUT_DIM) + ntile * 128;
        float* orow1 = out + ((size_t)(s * B_DIM + m0 + 8) * OUT_DIM) + ntile * 128;
        #pragma unroll
        for (int ni = 0; ni < 4; ++ni) {
            const int lcol = wn_idx * 32 + ni * 8 + col_in;
            const float b0 = s_bias[lcol];
            const float b1 = s_bias[lcol + 1];
            float2 v0, v1;
            v0.x = acc[mi][ni][0] + b0;
            v0.y = acc[mi][ni][1] + b1;
            v1.x = acc[mi][ni][2] + b0;
            v1.y = acc[mi][ni][3] + b1;
            *reinterpret_cast<float2*>(orow0 + lcol) = v0;
            *reinterpret_cast<float2*>(orow1 + lcol) = v1;
        }
    }
}

// ---------------------------------------------------------------------------
// Launch
// ---------------------------------------------------------------------------
extern "C" void kernel_launch(void* const* d_in, const int* in_sizes, int n_in,
                              void* d_out, int out_size)
{
    (void)in_sizes; (void)n_in; (void)out_size;
    const float* input  = (const float*)d_in[0];
    const float* wmu    = (const float*)d_in[1];
    const float* wrho   = (const float*)d_in[2];
    const float* bmu    = (const float*)d_in[3];
    const float* brho   = (const float*)d_in[4];
    const float* epsw   = (const float*)d_in[5];
    const float* epsb   = (const float*)d_in[6];
    float* out = (float*)d_out;

    cudaFuncSetAttribute(gemm_fused_kernel,
                         cudaFuncAttributeMaxDynamicSharedMemorySize,
                         GEMM_DYN_SMEM);

    // 8192 x-blocks + 1024 msp-blocks
    prep_kernel<<<9216, 256>>>(input, wmu, wrho);
    // (ntile=8, mtile=2, s=32) = 512 CTAs
    gemm_fused_kernel<<<dim3(8, 2, 32), 256, GEMM_DYN_SMEM>>>(
        epsw, bmu, brho, epsb, out);
}

// round 14
// speedup vs baseline: 1.2585x; 1.2585x over previous
#include <cuda_runtime.h>
#include <cuda_fp16.h>
#include <cstdint>

// Problem dims
#define S_DIM   32
#define B_DIM   256
#define IN_DIM  1024
#define OUT_DIM 1024

// ---------------------------------------------------------------------------
// Scratch (device globals; the only sanctioned scratch)
// ---------------------------------------------------------------------------
__device__ __align__(128) __half g_wf16[(size_t)S_DIM * OUT_DIM * IN_DIM];  // 67 MB
__device__ __align__(128) __half g_xf16[(size_t)S_DIM * B_DIM * IN_DIM];    // 17 MB

__device__ __forceinline__ float softplusf(float x) {
    return (x > 15.0f) ? x : log1pf(expf(x));
}

__device__ __forceinline__ uint32_t smem_to_u32(const void* smem_ptr) {
    uint32_t addr;
    asm("{ .reg .u64 tmp; cvta.to.shared.u64 tmp, %1; cvt.u32.u64 %0, tmp; }"
        : "=r"(addr) : "l"(smem_ptr));
    return addr;
}

__device__ __forceinline__ void cp_async16(uint32_t smem_dst, const void* gptr) {
    asm volatile("cp.async.cg.shared.global [%0], [%1], 16;"
                 :: "r"(smem_dst), "l"(gptr) : "memory");
}

__device__ __forceinline__ void ldmatrix_x4(uint32_t r[4], uint32_t addr) {
    asm volatile("ldmatrix.sync.aligned.m8n8.x4.shared.b16 {%0,%1,%2,%3}, [%4];"
                 : "=r"(r[0]), "=r"(r[1]), "=r"(r[2]), "=r"(r[3]) : "r"(addr));
}

__device__ __forceinline__ void mma16816(float c[4],
                                         const uint32_t a[4],
                                         uint32_t b0, uint32_t b1) {
    asm volatile(
        "mma.sync.aligned.m16n8k16.row.col.f32.f16.f16.f32 "
        "{%0,%1,%2,%3}, {%4,%5,%6,%7}, {%8,%9}, {%0,%1,%2,%3};"
        : "+f"(c[0]), "+f"(c[1]), "+f"(c[2]), "+f"(c[3])
        : "r"(a[0]), "r"(a[1]), "r"(a[2]), "r"(a[3]), "r"(b0), "r"(b1));
}

// SW128 swizzle: byte address of 16B-quad (row, colq) in a 128-row x 128B tile.
__device__ __forceinline__ uint32_t sw128(int row, int colq) {
    return ((uint32_t)row << 7) + ((uint32_t)((colq ^ (row & 7)) & 7) << 4);
}

// ---- mbarrier helpers ----
#define MBAR_INIT(addr, cnt) \
    asm volatile("mbarrier.init.shared.b64 [%0], %1;" \
                 :: "r"(addr), "r"((uint32_t)(cnt)) : "memory")

#define MBAR_ARRIVE(addr) \
    asm volatile("mbarrier.arrive.shared.b64 _, [%0];" :: "r"(addr) : "memory")

// .noinc: does NOT bump the expected count — plain async arrive on completion
// of this thread's prior cp.asyncs. (The inc-form deadlocks with init(256).)
#define CP_ASYNC_MBAR_ARRIVE_NOINC(addr) \
    asm volatile("cp.async.mbarrier.arrive.noinc.shared.b64 [%0];" :: "r"(addr) : "memory")

#define MBAR_WAIT_PARITY(addr, parity) do { \
    uint32_t _mbar = (uint32_t)(addr); \
    uint32_t _par  = (uint32_t)(parity); \
    uint32_t _done; \
    asm volatile( \
        "{\n\t.reg .pred p;\n\t" \
        "mbarrier.try_wait.parity.acquire.cta.shared::cta.b64 p, [%1], %2;\n\t" \
        "selp.b32 %0, 1, 0, p;\n\t}" \
        : "=r"(_done) : "r"(_mbar), "r"(_par) : "memory"); \
    if (!_done) { \
        asm volatile( \
            "{\n\t.reg .pred P1;\n\t" \
            "WAIT_LOOP_%=:\n\t" \
            "mbarrier.try_wait.parity.acquire.cta.shared::cta.b64 P1, [%0], %1, 0x989680;\n\t" \
            "@P1 bra.uni WAIT_DONE_%=;\n\t" \
            "bra.uni WAIT_LOOP_%=;\n\t" \
            "WAIT_DONE_%=:\n\t}" \
            :: "r"(_mbar), "r"(_par) : "memory"); \
    } \
} while(0)

// ---------------------------------------------------------------------------
// Kernel 1 (merged prep):
//   blocks [0,1024):    w_f16[s,o,i] = half(mu + softplus(rho)*eps_w)
//   blocks [1024,9216): x_f16 = half(input)
// ---------------------------------------------------------------------------
__global__ __launch_bounds__(256)
void prep_all_kernel(const float* __restrict__ input,
                     const float* __restrict__ wmu,
                     const float* __restrict__ wrho,
                     const float* __restrict__ epsw)
{
    if (blockIdx.x < 1024) {
        const int q  = blockIdx.x * 256 + threadIdx.x;   // 0..262143 quads
        const int mi = q * 4;

        const float4 m = *reinterpret_cast<const float4*>(wmu + mi);
        const float4 r = *reinterpret_cast<const float4*>(wrho + mi);
        float4 sg;
        sg.x = softplusf(r.x);
        sg.y = softplusf(r.y);
        sg.z = softplusf(r.z);
        sg.w = softplusf(r.w);

        const size_t plane = (size_t)OUT_DIM * IN_DIM;
        #pragma unroll 4
        for (int s = 0; s < S_DIM; ++s) {
            const float4 ew = *reinterpret_cast<const float4*>(epsw + s * plane + mi);
            float w0 = fmaf(sg.x, ew.x, m.x);
            float w1 = fmaf(sg.y, ew.y, m.y);
            float w2 = fmaf(sg.z, ew.z, m.z);
            float w3 = fmaf(sg.w, ew.w, m.w);
            __half2 h0 = __floats2half2_rn(w0, w1);
            __half2 h1 = __floats2half2_rn(w2, w3);
            uint2 o;
            o.x = *reinterpret_cast<unsigned*>(&h0);
            o.y = *reinterpret_cast<unsigned*>(&h1);
            *reinterpret_cast<uint2*>(g_wf16 + s * plane + mi) = o;
        }
    } else {
        const int e4 = (blockIdx.x - 1024) * 256 + threadIdx.x;  // 0..2097151
        const float4 x = *reinterpret_cast<const float4*>(input + (size_t)e4 * 4);
        __half2 h0 = __floats2half2_rn(x.x, x.y);
        __half2 h1 = __floats2half2_rn(x.z, x.w);
        uint2 o;
        o.x = *reinterpret_cast<unsigned*>(&h0);
        o.y = *reinterpret_cast<unsigned*>(&h1);
        reinterpret_cast<uint2*>(g_xf16)[e4] = o;
    }
}

// ---------------------------------------------------------------------------
// Kernel 2: per-sample GEMM via mma.sync (fp16 in / fp32 accum).
// CTA tile M=128 x N=128, K=1024 in 16 chunks of 64. 8 warps (2x4).
// 3-stage cp.async ring synchronized ENTIRELY by mbarriers (no __syncthreads
// in the mainloop): full[s] (count 256, .noinc cp.async arrivals) and
// free[s] (count 8, one lane-0 arrive per warp after its last ldmatrix).
// Warps flow independently -> no per-chunk convoy.
// Grid: (8, 2, 32) = 512 CTAs, 256 threads, 2 CTAs/SM.
// ---------------------------------------------------------------------------
#define KC 64
#define NCHUNK (IN_DIM / KC)          // 16
#define TILE_BYTES (128 * 128)        // 16 KB
#define STAGE_BYTES (2 * TILE_BYTES)  // A + B per stage
#define NSTAGE 3
#define GEMM_DYN_SMEM (1024 + NSTAGE * STAGE_BYTES)

__global__ __launch_bounds__(256, 2)
void gemm_f16_kernel(const float* __restrict__ bias_mu,
                     const float* __restrict__ bias_rho,
                     const float* __restrict__ eps_b,
                     float* __restrict__ out)
{
    extern __shared__ char dynsmem[];
    __shared__ float s_bias[128];
    __shared__ __align__(8) unsigned long long s_mbars[6];  // full0..2, free0..2

    const int tid = threadIdx.x;
    const int wid = tid >> 5;
    const int lid = tid & 31;
    const int ntile = blockIdx.x;   // 0..7
    const int mtile = blockIdx.y;   // 0..1
    const int s     = blockIdx.z;   // 0..31

    uint32_t base = smem_to_u32(dynsmem);
    base = (base + 1023u) & ~1023u;
    const uint32_t smA0 = base;
    const uint32_t smB0 = base + TILE_BYTES;

    const uint32_t mb0 = smem_to_u32(s_mbars);
    const uint32_t mb_full0 = mb0;          // +8*s
    const uint32_t mb_free0 = mb0 + 24;     // +8*s

    // Fused bias (before the init barrier so epilogue reads are safe).
    if (tid < 128) {
        const int o = ntile * 128 + tid;
        s_bias[tid] = fmaf(softplusf(bias_rho[o]), eps_b[s * OUT_DIM + o], bias_mu[o]);
    }

    if (tid == 0) {
        #pragma unroll
        for (int i = 0; i < 3; ++i) {
            MBAR_INIT(mb_full0 + 8 * i, 256);  // per-thread cp.async arrivals
            MBAR_INIT(mb_free0 + 8 * i, 8);    // per-warp reader arrivals
        }
    }
    __syncthreads();   // mbarriers + s_bias visible

    // Pre-arm free[2] so the first wait on it (issuing chunk 2) passes.
    if (lid == 0) MBAR_ARRIVE(mb_free0 + 8 * 2);

    const __half* Ag = g_xf16 + (size_t)(s * B_DIM + mtile * 128) * IN_DIM;
    const __half* Bg = g_wf16 + (size_t)(s * OUT_DIM + ntile * 128) * IN_DIM;

    // Copy slots: 4 quads per tile per thread (full 16KB tile per stage).
    uint32_t cp_dst[4];
    const __half* a_src[4];
    const __half* b_src[4];
    #pragma unroll
    for (int j = 0; j < 4; ++j) {
        const int q   = tid + j * 256;
        const int row = q >> 3;
        const int kq  = q & 7;
        cp_dst[j] = sw128(row, kq);
        a_src[j]  = Ag + (size_t)row * IN_DIM + kq * 8;
        b_src[j]  = Bg + (size_t)row * IN_DIM + kq * 8;
    }

    // Warp tiling: 2 (M) x 4 (N) warps; warp tile 64 x 32.
    const int wm_idx = wid >> 2;
    const int wn_idx = wid & 3;

    // XOR-folded ldmatrix bases: addr(ks) = base ^ (ks<<5).
    uint32_t a_base[4];
    #pragma unroll
    for (int mi = 0; mi < 4; ++mi) {
        const int row = wm_idx * 64 + mi * 16 + (lid & 15);
        a_base[mi] = sw128(row, lid >> 4);
    }
    uint32_t b_base[2];
    #pragma unroll
    for (int g = 0; g < 2; ++g) {
        const int row = wn_idx * 32 + g * 16 + ((lid >> 4) << 3) + (lid & 7);
        b_base[g] = sw128(row, (lid >> 3) & 1);
    }

    float acc[4][4][4];
    #pragma unroll
    for (int mi = 0; mi < 4; ++mi)
        #pragma unroll
        for (int ni = 0; ni < 4; ++ni)
            #pragma unroll
            for (int k = 0; k < 4; ++k)
                acc[mi][ni][k] = 0.0f;

    auto issue_chunk = [&](int c, int st) {
        const uint32_t sa = smA0 + (uint32_t)st * STAGE_BYTES;
        const uint32_t sb = smB0 + (uint32_t)st * STAGE_BYTES;
        #pragma unroll
        for (int j = 0; j < 4; ++j) {
            cp_async16(sa + cp_dst[j], a_src[j] + c * KC);
            cp_async16(sb + cp_dst[j], b_src[j] + c * KC);
        }
    };

    // Prologue: chunks 0,1 in flight; each thread signals its copy completion.
    issue_chunk(0, 0);
    CP_ASYNC_MBAR_ARRIVE_NOINC(mb_full0 + 8 * 0);
    issue_chunk(1, 1);
    CP_ASYNC_MBAR_ARRIVE_NOINC(mb_full0 + 8 * 1);

    int s_idx = 0;          // stage of chunk c (c % 3)
    int cnt3 = 0;
    uint32_t par = 0;       // (c/3)&1 — parity for BOTH waits this iteration
    for (int c = 0; c < NCHUNK; ++c) {
        // Data-ready for chunk c.
        MBAR_WAIT_PARITY(mb_full0 + 8 * s_idx, par);

        // Refill the ring: stage (c+2)%3 once its previous readers are done.
        if (c + 2 < NCHUNK) {
            int s2 = s_idx + 2; if (s2 >= NSTAGE) s2 -= NSTAGE;
            MBAR_WAIT_PARITY(mb_free0 + 8 * s2, par);
            issue_chunk(c + 2, s2);
            CP_ASYNC_MBAR_ARRIVE_NOINC(mb_full0 + 8 * s2);
        }

        const uint32_t sa = smA0 + (uint32_t)s_idx * STAGE_BYTES;
        const uint32_t sb = smB0 + (uint32_t)s_idx * STAGE_BYTES;

        #pragma unroll
        for (int ks = 0; ks < 4; ++ks) {
            const uint32_t kx = (uint32_t)(ks << 5);
            uint32_t ar[4][4];
            uint32_t br[2][4];
            #pragma unroll
            for (int mi = 0; mi < 4; ++mi)
                ldmatrix_x4(ar[mi], sa + (a_base[mi] ^ kx));
            #pragma unroll
            for (int g = 0; g < 2; ++g)
                ldmatrix_x4(br[g], sb + (b_base[g] ^ kx));

            // This warp's reads of stage s_idx are complete after ks==3 loads.
            if (ks == 3 && lid == 0) MBAR_ARRIVE(mb_free0 + 8 * s_idx);

            #pragma unroll
            for (int mi = 0; mi < 4; ++mi) {
                #pragma unroll
                for (int ni = 0; ni < 4; ++ni) {
                    const int g = ni >> 1;
                    const int h = (ni & 1) << 1;
                    mma16816(acc[mi][ni], ar[mi], br[g][h + 0], br[g][h + 1]);
                }
            }
        }

        if (++s_idx >= NSTAGE) s_idx -= NSTAGE;
        if (++cnt3 == 3) { cnt3 = 0; par ^= 1u; }
    }

    // Epilogue: add bias, store fp32 (registers only; no sync needed).
    const int row_in = (lid >> 2);
    const int col_in = (lid & 3) * 2;
    #pragma unroll
    for (int mi = 0; mi < 4; ++mi) {
        const int m0 = mtile * 128 + wm_idx * 64 + mi * 16 + row_in;
        float* orow0 = out + ((size_t)(s * B_DIM + m0)     * OUT_DIM) + ntile * 128;
        float* orow1 = out + ((size_t)(s * B_DIM + m0 + 8) * OUT_DIM) + ntile * 128;
        #pragma unroll
        for (int ni = 0; ni < 4; ++ni) {
            const int lcol = wn_idx * 32 + ni * 8 + col_in;
            const float b0 = s_bias[lcol];
            const float b1 = s_bias[lcol + 1];
            float2 v0, v1;
            v0.x = acc[mi][ni][0] + b0;
            v0.y = acc[mi][ni][1] + b1;
            v1.x = acc[mi][ni][2] + b0;
            v1.y = acc[mi][ni][3] + b1;
            *reinterpret_cast<float2*>(orow0 + lcol) = v0;
            *reinterpret_cast<float2*>(orow1 + lcol) = v1;
        }
    }
}

// ---------------------------------------------------------------------------
// Launch
// ---------------------------------------------------------------------------
extern "C" void kernel_launch(void* const* d_in, const int* in_sizes, int n_in,
                              void* d_out, int out_size)
{
    (void)in_sizes; (void)n_in; (void)out_size;
    const float* input  = (const float*)d_in[0];
    const float* wmu    = (const float*)d_in[1];
    const float* wrho   = (const float*)d_in[2];
    const float* bmu    = (const float*)d_in[3];
    const float* brho   = (const float*)d_in[4];
    const float* epsw   = (const float*)d_in[5];
    const float* epsb   = (const float*)d_in[6];
    float* out = (float*)d_out;

    cudaFuncSetAttribute(gemm_f16_kernel,
                         cudaFuncAttributeMaxDynamicSharedMemorySize,
                         GEMM_DYN_SMEM);

    prep_all_kernel<<<9216, 256>>>(input, wmu, wrho, epsw);
    gemm_f16_kernel<<<dim3(8, 2, 32), 256, GEMM_DYN_SMEM>>>(bmu, brho, epsb, out);
}